// round 13
// baseline (speedup 1.0000x reference)
#include <cuda_runtime.h>
#include <mma.h>
using namespace nvcuda;

#define NAB 20000
#define NAG 20000
#define NTOT 40000
#define FDIM 256
#define EAB 320000
#define EAG 320000
#define ED 640000
#define ETOT (EAB + EAG + ED)
#define EPSV 1e-5f
#define MPAD 40192  // 2*157*128, room for dual-GEMM full-tile stores
#define CSRN (3 * NTOT)
#define SCAN_BLOCKS ((CSRN + 1023) / 1024)
#define ALD 20   // padded As leading dim
#define BLD 132  // padded Bs leading dim

// ---------------- scratch (device globals; no allocs) ----------------
__device__ float g_h[NTOT * FDIM];    // 0
__device__ float g_xa[NTOT * FDIM];   // 1
__device__ float g_xb[NTOT * FDIM];   // 2
__device__ float g_tmp[MPAD * FDIM];  // 3
__device__ float g_deg[NTOT];
__device__ float g_es[NTOT];
__device__ float g_ed[NTOT];
__device__ float g_csum[4][FDIM];
__device__ float g_csq[4][FDIM];
__device__ int g_cnt[CSRN];
__device__ int g_rowg[CSRN + 1];
__device__ int g_bsum[SCAN_BLOCKS];
__device__ int g_srt[ETOT];

__device__ __forceinline__ float* BUF(int which) {
    switch (which) {
        case 0: return g_h;
        case 1: return g_xa;
        case 2: return g_xb;
        default: return g_tmp;
    }
}

__device__ __forceinline__ float lrelu(float x) { return x > 0.f ? x : 0.2f * x; }

// ---------------- batched CSR build ----------------
__global__ void k_zero_csr() {
    int i = blockIdx.x * blockDim.x + threadIdx.x;
    if (i < CSRN) g_cnt[i] = 0;
}
__global__ void k_hist_all(const int* __restrict__ dab, const int* __restrict__ dag,
                           const int* __restrict__ dd) {
    int e = blockIdx.x * blockDim.x + threadIdx.x;
    if (e < EAB) atomicAdd(&g_cnt[0 * NTOT + dab[e]], 1);
    else if (e < EAB + EAG) atomicAdd(&g_cnt[1 * NTOT + dag[e - EAB]], 1);
    else if (e < ETOT) atomicAdd(&g_cnt[2 * NTOT + dd[e - EAB - EAG]], 1);
}
__global__ void k_scan1() {
    __shared__ int wsum[32];
    int gi = blockIdx.x * 1024 + threadIdx.x;
    int v = (gi < CSRN) ? g_cnt[gi] : 0;
    if (gi < NAB) g_deg[gi] = rsqrtf((float)(v + 1));
    else if (gi >= NTOT && gi < NTOT + NAG) g_deg[NAB + gi - NTOT] = rsqrtf((float)(v + 1));
    // fused zero of BN stat slots 0-3 (first block covers 1024 = 4*FDIM)
    if (gi < 4 * FDIM) {
        ((float*)g_csum)[gi] = 0.f;
        ((float*)g_csq)[gi] = 0.f;
    }
    int lane = threadIdx.x & 31, wid = threadIdx.x >> 5;
    int inc = v;
#pragma unroll
    for (int o = 1; o < 32; o <<= 1) {
        int u = __shfl_up_sync(0xFFFFFFFFu, inc, o);
        if (lane >= o) inc += u;
    }
    if (lane == 31) wsum[wid] = inc;
    __syncthreads();
    if (wid == 0) {
        int w = wsum[lane];
#pragma unroll
        for (int o = 1; o < 32; o <<= 1) {
            int u = __shfl_up_sync(0xFFFFFFFFu, w, o);
            if (lane >= o) w += u;
        }
        wsum[lane] = w;
    }
    __syncthreads();
    int ex = inc - v + (wid ? wsum[wid - 1] : 0);
    if (gi < CSRN) g_rowg[gi] = ex;
    if (threadIdx.x == 1023) g_bsum[blockIdx.x] = ex + v;
}
__global__ void k_scan2() {
    __shared__ int ws[4];
    int t = threadIdx.x;
    int lane = t & 31, wid = t >> 5;
    int v = (t < SCAN_BLOCKS) ? g_bsum[t] : 0;
    int inc = v;
#pragma unroll
    for (int o = 1; o < 32; o <<= 1) {
        int u = __shfl_up_sync(0xFFFFFFFFu, inc, o);
        if (lane >= o) inc += u;
    }
    if (lane == 31) ws[wid] = inc;
    __syncthreads();
    int add = 0;
    for (int i = 0; i < wid; i++) add += ws[i];
    if (t < SCAN_BLOCKS) g_bsum[t] = inc - v + add;
}
__global__ void k_scan3() {
    int gi = blockIdx.x * 1024 + threadIdx.x;
    if (gi < CSRN) {
        int r = g_rowg[gi] + g_bsum[blockIdx.x];
        g_rowg[gi] = r;
        g_cnt[gi] = r;
    }
    if (gi == 0) g_rowg[CSRN] = ETOT;
}
__global__ void k_fill_all(const int* __restrict__ eab, const int* __restrict__ eag,
                           const int* __restrict__ ed) {
    int e = blockIdx.x * blockDim.x + threadIdx.x;
    int g, le;
    const int* src;
    const int* dst;
    if (e < EAB) { g = 0; le = e; src = eab; dst = eab + EAB; }
    else if (e < EAB + EAG) { g = 1; le = e - EAB; src = eag; dst = eag + EAG; }
    else if (e < ETOT) { g = 2; le = e - EAB - EAG; src = ed; dst = ed + ED; }
    else return;
    int d = dst[le];
    int pos = atomicAdd(&g_cnt[g * NTOT + d], 1);
    g_srt[pos] = src[le];
}

__global__ void k_zero_esed() {
    int i = blockIdx.x * blockDim.x + threadIdx.x;
    if (i < NTOT) {
        g_es[i] = 0.f;
        g_ed[i] = 0.f;
    }
}

// ---------------- TF32 wmma GEMM core ----------------
// computes g_tmp[outrow0 + 0..M) = A[0..M) @ B; optional fused es/ed dot epilogue
__device__ __forceinline__ void gemm_body(const float* __restrict__ A,
                                          const float* __restrict__ B, int M, int outrow0,
                                          int by, int bx, const float* __restrict__ a_s,
                                          const float* __restrict__ a_d) {
    __shared__ alignas(16) float As[2][128][ALD];
    __shared__ alignas(16) float Bs[2][16][BLD];
    int t = threadIdx.x;
    int wid = t >> 5;
    int wr = wid >> 2;
    int wc = wid & 3;
    int brow0 = by * 128;
    int bcol0 = bx * 128;

    wmma::fragment<wmma::accumulator, 16, 16, 8, float> c[4][2];
#pragma unroll
    for (int i = 0; i < 4; i++)
#pragma unroll
        for (int j = 0; j < 2; j++) wmma::fill_fragment(c[i][j], 0.0f);

    int af0 = t * 2, af1 = t * 2 + 1;
    int ar0 = af0 >> 2, ac0 = (af0 & 3) << 2;
    int ar1 = af1 >> 2, ac1 = (af1 & 3) << 2;
    int br0 = af0 >> 5, bc0 = (af0 & 31) << 2;
    int br1 = af1 >> 5, bc1 = (af1 & 31) << 2;

#define CVT4(v)                                  \
    do {                                         \
        (v).x = wmma::__float_to_tf32((v).x);    \
        (v).y = wmma::__float_to_tf32((v).y);    \
        (v).z = wmma::__float_to_tf32((v).z);    \
        (v).w = wmma::__float_to_tf32((v).w);    \
    } while (0)

    {
        float4 z = make_float4(0.f, 0.f, 0.f, 0.f);
        float4 a0v = (brow0 + ar0 < M) ? *(const float4*)(A + (brow0 + ar0) * 256 + ac0) : z;
        float4 a1v = (brow0 + ar1 < M) ? *(const float4*)(A + (brow0 + ar1) * 256 + ac1) : z;
        float4 b0v = *(const float4*)(B + br0 * 256 + bcol0 + bc0);
        float4 b1v = *(const float4*)(B + br1 * 256 + bcol0 + bc1);
        CVT4(a0v); CVT4(a1v); CVT4(b0v); CVT4(b1v);
        *(float4*)&As[0][ar0][ac0] = a0v;
        *(float4*)&As[0][ar1][ac1] = a1v;
        *(float4*)&Bs[0][br0][bc0] = b0v;
        *(float4*)&Bs[0][br1][bc1] = b1v;
    }
    __syncthreads();
    int cur = 0;
    for (int k0 = 16; k0 <= 256; k0 += 16) {
        float4 a0v, a1v, b0v, b1v;
        if (k0 < 256) {
            float4 z = make_float4(0.f, 0.f, 0.f, 0.f);
            a0v = (brow0 + ar0 < M) ? *(const float4*)(A + (brow0 + ar0) * 256 + k0 + ac0) : z;
            a1v = (brow0 + ar1 < M) ? *(const float4*)(A + (brow0 + ar1) * 256 + k0 + ac1) : z;
            b0v = *(const float4*)(B + (k0 + br0) * 256 + bcol0 + bc0);
            b1v = *(const float4*)(B + (k0 + br1) * 256 + bcol0 + bc1);
        }
#pragma unroll
        for (int kk = 0; kk < 16; kk += 8) {
            wmma::fragment<wmma::matrix_a, 16, 16, 8, wmma::precision::tf32, wmma::row_major> a[4];
            wmma::fragment<wmma::matrix_b, 16, 16, 8, wmma::precision::tf32, wmma::row_major> b[2];
#pragma unroll
            for (int i = 0; i < 4; i++)
                wmma::load_matrix_sync(a[i], &As[cur][wr * 64 + i * 16][kk], ALD);
#pragma unroll
            for (int j = 0; j < 2; j++)
                wmma::load_matrix_sync(b[j], &Bs[cur][kk][wc * 32 + j * 16], BLD);
#pragma unroll
            for (int i = 0; i < 4; i++)
#pragma unroll
                for (int j = 0; j < 2; j++) wmma::mma_sync(c[i][j], a[i], b[j], c[i][j]);
        }
        if (k0 < 256) {
            int nxt = cur ^ 1;
            CVT4(a0v); CVT4(a1v); CVT4(b0v); CVT4(b1v);
            *(float4*)&As[nxt][ar0][ac0] = a0v;
            *(float4*)&As[nxt][ar1][ac1] = a1v;
            *(float4*)&Bs[nxt][br0][bc0] = b0v;
            *(float4*)&Bs[nxt][br1][bc1] = b1v;
            __syncthreads();
            cur = nxt;
        }
    }
#pragma unroll
    for (int i = 0; i < 4; i++)
#pragma unroll
        for (int j = 0; j < 2; j++)
            wmma::store_matrix_sync(
                g_tmp + (long)(outrow0 + brow0 + wr * 64 + i * 16) * 256 + bcol0 + wc * 32 +
                    j * 16,
                c[i][j], 256, wmma::mem_row_major);
#undef CVT4

    // fused GAT logit epilogue: es += h.a_s, ed += h.a_d over this block's col tile.
    // Stage accumulator tiles through per-warp SMEM (reuse Bs after barrier).
    if (a_s) {
        __syncthreads();  // all warps done with Bs mainloop reads
        float* stg = ((float*)Bs) + wid * (16 * 20);
        int lane = t & 31;
        int r = lane >> 1;    // tile row 0..15
        int half = lane & 1;  // 8-col half
#pragma unroll
        for (int i = 0; i < 4; i++) {
            float ps = 0.f, pd = 0.f;
#pragma unroll
            for (int j = 0; j < 2; j++) {
                wmma::store_matrix_sync(stg, c[i][j], 20, wmma::mem_row_major);
                __syncwarp();
                int cb = bcol0 + wc * 32 + j * 16 + half * 8;
                float4 as0 = *(const float4*)(a_s + cb);
                float4 as1 = *(const float4*)(a_s + cb + 4);
                float4 ad0 = *(const float4*)(a_d + cb);
                float4 ad1 = *(const float4*)(a_d + cb + 4);
                const float* rp = stg + r * 20 + half * 8;
                ps += rp[0] * as0.x + rp[1] * as0.y + rp[2] * as0.z + rp[3] * as0.w +
                      rp[4] * as1.x + rp[5] * as1.y + rp[6] * as1.z + rp[7] * as1.w;
                pd += rp[0] * ad0.x + rp[1] * ad0.y + rp[2] * ad0.z + rp[3] * ad0.w +
                      rp[4] * ad1.x + rp[5] * ad1.y + rp[6] * ad1.z + rp[7] * ad1.w;
                __syncwarp();
            }
            ps += __shfl_xor_sync(0xFFFFFFFFu, ps, 1);
            pd += __shfl_xor_sync(0xFFFFFFFFu, pd, 1);
            if (half == 0) {
                int grow = brow0 + wr * 64 + i * 16 + r;
                if (grow < M) {
                    atomicAdd(&g_es[grow], ps);
                    atomicAdd(&g_ed[grow], pd);
                }
            }
        }
    }
}

// single GEMM (+ optional fused dots): g_tmp = A @ B
__global__ void __launch_bounds__(256, 2)
k_gemm(const float* __restrict__ Aext, int awhich, const float* __restrict__ B, int M,
       const float* __restrict__ a_s, const float* __restrict__ a_d) {
    const float* A = (awhich < 0) ? Aext : BUF(awhich);
    gemm_body(A, B, M, 0, blockIdx.y, blockIdx.x, a_s, a_d);
}
// dual GCN GEMM
__global__ void __launch_bounds__(256, 2)
k_gemm2(const float* __restrict__ x_ab, const float* __restrict__ W_ab,
        const float* __restrict__ x_ag, const float* __restrict__ W_ag) {
    if (blockIdx.z == 0) gemm_body(x_ab, W_ab, NAB, 0, blockIdx.y, blockIdx.x, nullptr, nullptr);
    else gemm_body(x_ag, W_ag, NAG, NAB, blockIdx.y, blockIdx.x, nullptr, nullptr);
}

// ---------------- merged GCN pull: warp per dst over both graphs ----------------
__global__ void k_gcn_pull2(const float* __restrict__ b_ab, const float* __restrict__ b_ag) {
    int w = (blockIdx.x * blockDim.x + threadIdx.x) >> 5;
    int lane = threadIdx.x & 31;
    if (w >= NTOT) return;
    int g, local, tmprow;
    const float* b;
    if (w < NAB) { g = 0; local = w; tmprow = 0; b = b_ab; }
    else { g = 1; local = w - NAB; tmprow = NAB; b = b_ag; }
    int rb = g * NTOT;
    int r0 = g_rowg[rb + local], r1 = g_rowg[rb + local + 1];
    float dd = g_deg[w];
    const float4* hp = (const float4*)(g_tmp + (long)(tmprow + local) * FDIM);
    float4 a0 = hp[lane];
    float4 a1 = hp[lane + 32];
    float sc = dd * dd;
    a0.x *= sc; a0.y *= sc; a0.z *= sc; a0.w *= sc;
    a1.x *= sc; a1.y *= sc; a1.z *= sc; a1.w *= sc;
    int degbase = (g == 0) ? 0 : NAB;
    for (int j = r0; j < r1; j++) {
        int s = g_srt[j];
        float nm = g_deg[degbase + s] * dd;
        const float4* sp = (const float4*)(g_tmp + (long)(tmprow + s) * FDIM);
        float4 v0 = sp[lane];
        float4 v1 = sp[lane + 32];
        a0.x += v0.x * nm; a0.y += v0.y * nm; a0.z += v0.z * nm; a0.w += v0.w * nm;
        a1.x += v1.x * nm; a1.y += v1.y * nm; a1.z += v1.z * nm; a1.w += v1.w * nm;
    }
    float4 b0 = *((const float4*)b + lane);
    float4 b1 = *((const float4*)b + lane + 32);
    a0.x += b0.x; a0.y += b0.y; a0.z += b0.z; a0.w += b0.w;
    a1.x += b1.x; a1.y += b1.y; a1.z += b1.z; a1.w += b1.w;
    float4* op = (float4*)(g_h + (long)w * FDIM);
    op[lane] = a0;
    op[lane + 32] = a1;
}

// ---------------- BN ----------------
__global__ void k_zero_stats() {
    g_csum[blockIdx.x][threadIdx.x] = 0.f;
    g_csq[blockIdx.x][threadIdx.x] = 0.f;
}
__global__ void k_colstats2() {
    int grp = blockIdx.x >> 8;
    int blk = blockIdx.x & 255;
    const float* x = grp ? (g_h + NAB * FDIM) : g_h;
    int nrows = grp ? NAG : NAB;
    int col = threadIdx.x;
    float s = 0.f, q = 0.f;
    for (int r = blk; r < nrows; r += 256) {
        float v = x[r * FDIM + col];
        s += v;
        q += v * v;
    }
    atomicAdd(&g_csum[grp][col], s);
    atomicAdd(&g_csq[grp][col], q);
}
__global__ void k_bn_relu2(const float* __restrict__ g_ab, const float* __restrict__ be_ab,
                           const float* __restrict__ g_ag, const float* __restrict__ be_ag) {
    int idx = blockIdx.x * blockDim.x + threadIdx.x;
    if (idx >= NTOT * 64) return;
    int row = idx >> 6;
    int slot = (row < NAB) ? 0 : 1;
    float n = (float)(slot ? NAG : NAB);
    const float* g = slot ? g_ag : g_ab;
    const float* be = slot ? be_ag : be_ab;
    int f = (idx & 63) << 2;
    float4 v = *((float4*)g_h + idx);
    float* pv = &v.x;
#pragma unroll
    for (int j = 0; j < 4; j++) {
        float mu = g_csum[slot][f + j] / n;
        float var = g_csq[slot][f + j] / n - mu * mu;
        float o = (pv[j] - mu) * rsqrtf(var + EPSV) * g[f + j] + be[f + j];
        pv[j] = o > 0.f ? o : 0.f;
    }
    *((float4*)g_h + idx) = v;
}
__global__ void k_colstats4() {
    int grp = blockIdx.x >> 8;
    int blk = blockIdx.x & 255;
    const float* x;
    int nrows;
    switch (grp) {
        case 0: x = g_xb; nrows = NAB; break;
        case 1: x = g_xb + NAB * FDIM; nrows = NAG; break;
        case 2: x = g_h; nrows = NAB; break;
        default: x = g_h + NAB * FDIM; nrows = NAG; break;
    }
    int col = threadIdx.x;
    float s = 0.f, q = 0.f;
    for (int r = blk; r < nrows; r += 256) {
        float v = x[r * FDIM + col];
        s += v;
        q += v * v;
    }
    atomicAdd(&g_csum[grp][col], s);
    atomicAdd(&g_csq[grp][col], q);
}

// ---------------- GAT pull ----------------
__global__ void k_gat_pull(int accwhich, const float* __restrict__ b, int dorelu) {
    int w = (blockIdx.x * blockDim.x + threadIdx.x) >> 5;
    int lane = threadIdx.x & 31;
    if (w >= NTOT) return;
    int rb = 2 * NTOT;
    int r0 = g_rowg[rb + w], r1 = g_rowg[rb + w + 1];
    float edd = g_ed[w];
    float eself = lrelu(g_es[w] + edd);
    float m = eself;
    for (int j = r0 + lane; j < r1; j += 32) {
        m = fmaxf(m, lrelu(g_es[g_srt[j]] + edd));
    }
#pragma unroll
    for (int o = 16; o; o >>= 1) m = fmaxf(m, __shfl_xor_sync(0xFFFFFFFFu, m, o));
    float exs = __expf(eself - m);
    float ssum = exs;
    const float4* hp = (const float4*)(g_tmp + (long)w * FDIM);
    float4 a0 = hp[lane];
    float4 a1 = hp[lane + 32];
    a0.x *= exs; a0.y *= exs; a0.z *= exs; a0.w *= exs;
    a1.x *= exs; a1.y *= exs; a1.z *= exs; a1.w *= exs;
    for (int j = r0; j < r1; j++) {
        int s = g_srt[j];
        float ex = __expf(lrelu(g_es[s] + edd) - m);
        ssum += ex;
        const float4* sp = (const float4*)(g_tmp + (long)s * FDIM);
        float4 v0 = sp[lane];
        float4 v1 = sp[lane + 32];
        a0.x += v0.x * ex; a0.y += v0.y * ex; a0.z += v0.z * ex; a0.w += v0.w * ex;
        a1.x += v1.x * ex; a1.y += v1.y * ex; a1.z += v1.z * ex; a1.w += v1.w * ex;
    }
    float inv = 1.0f / ssum;
    float4 b0 = *((const float4*)b + lane);
    float4 b1 = *((const float4*)b + lane + 32);
    a0.x = a0.x * inv + b0.x; a0.y = a0.y * inv + b0.y;
    a0.z = a0.z * inv + b0.z; a0.w = a0.w * inv + b0.w;
    a1.x = a1.x * inv + b1.x; a1.y = a1.y * inv + b1.y;
    a1.z = a1.z * inv + b1.z; a1.w = a1.w * inv + b1.w;
    if (dorelu) {
        a0.x = fmaxf(a0.x, 0.f); a0.y = fmaxf(a0.y, 0.f);
        a0.z = fmaxf(a0.z, 0.f); a0.w = fmaxf(a0.w, 0.f);
        a1.x = fmaxf(a1.x, 0.f); a1.y = fmaxf(a1.y, 0.f);
        a1.z = fmaxf(a1.z, 0.f); a1.w = fmaxf(a1.w, 0.f);
    }
    float4* op = (float4*)(BUF(accwhich) + (long)w * FDIM);
    op[lane] = a0;
    op[lane + 32] = a1;
}

// ---------------- final heads (grid = NTOT) ----------------
__global__ void k_head2(const float* __restrict__ g2, const float* __restrict__ be2,
                        const float* __restrict__ W_fc, const float* __restrict__ b_fc,
                        const float* __restrict__ ag_g2, const float* __restrict__ ag_be2,
                        const float* __restrict__ W_agfc, const float* __restrict__ b_agfc,
                        float* __restrict__ out) {
    __shared__ float red[8];
    int row = blockIdx.x;
    int t = threadIdx.x;
    int lane = t & 31, wid = t >> 5;
    const float *xpart, *hpart, *g, *be, *W, *b;
    int slot_x, slot_h, lrow;
    if (row < NAB) {
        lrow = row;
        xpart = g_xb; hpart = g_h;
        slot_x = 0; slot_h = 2;
        g = g2; be = be2; W = W_fc; b = b_fc;
    } else {
        lrow = row - NAB;
        xpart = g_xb + NAB * FDIM; hpart = g_h + NAB * FDIM;
        slot_x = 1; slot_h = 3;
        g = ag_g2; be = ag_be2; W = W_agfc; b = b_agfc;
    }
    float n = (float)NAB;  // NAB == NAG
    float mu1 = g_csum[slot_x][t] / n;
    float var1 = g_csq[slot_x][t] / n - mu1 * mu1;
    float v1 = (xpart[lrow * FDIM + t] - mu1) * rsqrtf(var1 + EPSV) * g[t] + be[t];
    v1 = v1 > 0.f ? v1 : 0.f;
    float mu2 = g_csum[slot_h][t] / n;
    float var2 = g_csq[slot_h][t] / n - mu2 * mu2;
    float v2 = (hpart[lrow * FDIM + t] - mu2) * rsqrtf(var2 + EPSV) * g[FDIM + t] + be[FDIM + t];
    v2 = v2 > 0.f ? v2 : 0.f;
    float p = v1 * W[t] + v2 * W[FDIM + t];
#pragma unroll
    for (int o = 16; o; o >>= 1) p += __shfl_xor_sync(0xFFFFFFFFu, p, o);
    if (lane == 0) red[wid] = p;
    __syncthreads();
    if (t == 0) {
        float acc = red[0];
#pragma unroll
        for (int i = 1; i < 8; i++) acc += red[i];
        out[row] = acc + b[0];
    }
}

// ---------------- host orchestration (launches ONLY) ----------------
static void run_gat(int inwhich, const float* W, const float* a_s, const float* a_d,
                    const float* b, int accwhich, int dorelu) {
    k_zero_esed<<<(NTOT + 255) / 256, 256>>>();
    dim3 gg(2, (NTOT + 127) / 128);
    k_gemm<<<gg, 256>>>(nullptr, inwhich, W, NTOT, a_s, a_d);
    k_gat_pull<<<(NTOT + 7) / 8, 256>>>(accwhich, b, dorelu);
}

extern "C" void kernel_launch(void* const* d_in, const int* in_sizes, int n_in, void* d_out,
                              int out_size) {
    const float* x_ab = (const float*)d_in[0];
    const float* x_ag = (const float*)d_in[1];
    const float* W_gcn = (const float*)d_in[2];
    const float* b_gcn = (const float*)d_in[3];
    const float* g1 = (const float*)d_in[4];
    const float* be1 = (const float*)d_in[5];
    const float* W_aggcn = (const float*)d_in[6];
    const float* b_aggcn = (const float*)d_in[7];
    const float* ag_g1 = (const float*)d_in[8];
    const float* ag_be1 = (const float*)d_in[9];
    const float* W_gat = (const float*)d_in[10];
    const float* a_src = (const float*)d_in[11];
    const float* a_dst = (const float*)d_in[12];
    const float* b_gat = (const float*)d_in[13];
    const float* W_gat2 = (const float*)d_in[14];
    const float* a_src2 = (const float*)d_in[15];
    const float* a_dst2 = (const float*)d_in[16];
    const float* b_gat2 = (const float*)d_in[17];
    const float* ag_g2 = (const float*)d_in[18];
    const float* ag_be2 = (const float*)d_in[19];
    const float* W_agfc = (const float*)d_in[20];
    const float* b_agfc = (const float*)d_in[21];
    const float* g2 = (const float*)d_in[22];
    const float* be2 = (const float*)d_in[23];
    const float* W_fc = (const float*)d_in[24];
    const float* b_fc = (const float*)d_in[25];
    const int* e_ab = (const int*)d_in[26];
    const int* e_ag = (const int*)d_in[27];
    const int* e_d = (const int*)d_in[28];
    float* out = (float*)d_out;

    // batched CSR build (all 3 graphs, global prefix; scan1 also zeroes BN stats)
    k_zero_csr<<<(CSRN + 255) / 256, 256>>>();
    k_hist_all<<<(ETOT + 255) / 256, 256>>>(e_ab + EAB, e_ag + EAG, e_d + ED);
    k_scan1<<<SCAN_BLOCKS, 1024>>>();
    k_scan2<<<1, 128>>>();
    k_scan3<<<SCAN_BLOCKS, 1024>>>();
    k_fill_all<<<(ETOT + 255) / 256, 256>>>(e_ab, e_ag, e_d);

    // both GCNs fused
    {
        dim3 gg(2, (NAB + 127) / 128, 2);
        k_gemm2<<<gg, 256>>>(x_ab, W_gcn, x_ag, W_aggcn);
        k_gcn_pull2<<<(NTOT + 7) / 8, 256>>>(b_gcn, b_aggcn);
        k_colstats2<<<512, 256>>>();
        k_bn_relu2<<<(NTOT * 64 + 255) / 256, 256>>>(g1, be1, ag_g1, ag_be1);
    }

    // GAT layer 1: g_h(0) -> g_xa(1), relu (dots fused into GEMM epilogue)
    run_gat(0, W_gat, a_src, a_dst, b_gat, 1, 1);
    // GAT layer 2: g_xa(1) -> g_xb(2), no relu
    run_gat(1, W_gat2, a_src2, a_dst2, b_gat2, 2, 0);

    // head stats + heads
    k_zero_stats<<<4, 256>>>();
    k_colstats4<<<1024, 256>>>();
    k_head2<<<NTOT, 256>>>(g2, be2, W_fc, b_fc, ag_g2, ag_be2, W_agfc, b_agfc, out);
}

// round 14
// speedup vs baseline: 1.0107x; 1.0107x over previous
#include <cuda_runtime.h>
#include <mma.h>
using namespace nvcuda;

#define NAB 20000
#define NAG 20000
#define NTOT 40000
#define FDIM 256
#define EAB 320000
#define EAG 320000
#define ED 640000
#define ETOT (EAB + EAG + ED)
#define EPSV 1e-5f
#define MPAD 40192  // 2*157*128, room for dual-GEMM full-tile stores
#define CSRN (3 * NTOT)
#define SCAN_BLOCKS ((CSRN + 1023) / 1024)
#define ALD 20   // padded As leading dim
#define BLD 132  // padded Bs leading dim

// ---------------- scratch (device globals; no allocs) ----------------
__device__ float g_h[NTOT * FDIM];    // 0
__device__ float g_xa[NTOT * FDIM];   // 1
__device__ float g_xb[NTOT * FDIM];   // 2
__device__ float g_tmp[MPAD * FDIM];  // 3
__device__ float g_deg[NTOT];
__device__ float g_es[NTOT];
__device__ float g_ed[NTOT];
__device__ float g_csum[4][FDIM];
__device__ float g_csq[4][FDIM];
__device__ int g_cnt[CSRN];
__device__ int g_rowg[CSRN + 1];
__device__ int g_bsum[SCAN_BLOCKS];
__device__ int g_srt[ETOT];

__device__ __forceinline__ float* BUF(int which) {
    switch (which) {
        case 0: return g_h;
        case 1: return g_xa;
        case 2: return g_xb;
        default: return g_tmp;
    }
}

__device__ __forceinline__ float lrelu(float x) { return x > 0.f ? x : 0.2f * x; }

// ---------------- batched CSR build ----------------
__global__ void k_zero_csr() {
    int i = blockIdx.x * blockDim.x + threadIdx.x;
    if (i < CSRN) g_cnt[i] = 0;
}
__global__ void k_hist_all(const int* __restrict__ dab, const int* __restrict__ dag,
                           const int* __restrict__ dd) {
    int e = blockIdx.x * blockDim.x + threadIdx.x;
    if (e < EAB) atomicAdd(&g_cnt[0 * NTOT + dab[e]], 1);
    else if (e < EAB + EAG) atomicAdd(&g_cnt[1 * NTOT + dag[e - EAB]], 1);
    else if (e < ETOT) atomicAdd(&g_cnt[2 * NTOT + dd[e - EAB - EAG]], 1);
}
__global__ void k_scan1() {
    __shared__ int wsum[32];
    int gi = blockIdx.x * 1024 + threadIdx.x;
    int v = (gi < CSRN) ? g_cnt[gi] : 0;
    if (gi < NAB) g_deg[gi] = rsqrtf((float)(v + 1));
    else if (gi >= NTOT && gi < NTOT + NAG) g_deg[NAB + gi - NTOT] = rsqrtf((float)(v + 1));
    // fused zero of BN stat slots 0-3 (first block covers 1024 = 4*FDIM)
    if (gi < 4 * FDIM) {
        ((float*)g_csum)[gi] = 0.f;
        ((float*)g_csq)[gi] = 0.f;
    }
    int lane = threadIdx.x & 31, wid = threadIdx.x >> 5;
    int inc = v;
#pragma unroll
    for (int o = 1; o < 32; o <<= 1) {
        int u = __shfl_up_sync(0xFFFFFFFFu, inc, o);
        if (lane >= o) inc += u;
    }
    if (lane == 31) wsum[wid] = inc;
    __syncthreads();
    if (wid == 0) {
        int w = wsum[lane];
#pragma unroll
        for (int o = 1; o < 32; o <<= 1) {
            int u = __shfl_up_sync(0xFFFFFFFFu, w, o);
            if (lane >= o) w += u;
        }
        wsum[lane] = w;
    }
    __syncthreads();
    int ex = inc - v + (wid ? wsum[wid - 1] : 0);
    if (gi < CSRN) g_rowg[gi] = ex;
    if (threadIdx.x == 1023) g_bsum[blockIdx.x] = ex + v;
}
__global__ void k_scan2() {
    __shared__ int ws[4];
    int t = threadIdx.x;
    int lane = t & 31, wid = t >> 5;
    int v = (t < SCAN_BLOCKS) ? g_bsum[t] : 0;
    int inc = v;
#pragma unroll
    for (int o = 1; o < 32; o <<= 1) {
        int u = __shfl_up_sync(0xFFFFFFFFu, inc, o);
        if (lane >= o) inc += u;
    }
    if (lane == 31) ws[wid] = inc;
    __syncthreads();
    int add = 0;
    for (int i = 0; i < wid; i++) add += ws[i];
    if (t < SCAN_BLOCKS) g_bsum[t] = inc - v + add;
}
__global__ void k_scan3() {
    int gi = blockIdx.x * 1024 + threadIdx.x;
    if (gi < CSRN) {
        int r = g_rowg[gi] + g_bsum[blockIdx.x];
        g_rowg[gi] = r;
        g_cnt[gi] = r;
    }
    if (gi == 0) g_rowg[CSRN] = ETOT;
}
__global__ void k_fill_all(const int* __restrict__ eab, const int* __restrict__ eag,
                           const int* __restrict__ ed) {
    int e = blockIdx.x * blockDim.x + threadIdx.x;
    int g, le;
    const int* src;
    const int* dst;
    if (e < EAB) { g = 0; le = e; src = eab; dst = eab + EAB; }
    else if (e < EAB + EAG) { g = 1; le = e - EAB; src = eag; dst = eag + EAG; }
    else if (e < ETOT) { g = 2; le = e - EAB - EAG; src = ed; dst = ed + ED; }
    else return;
    int d = dst[le];
    int pos = atomicAdd(&g_cnt[g * NTOT + d], 1);
    g_srt[pos] = src[le];
}

// ---------------- TF32 wmma GEMM core ----------------
__device__ __forceinline__ void gemm_body(const float* __restrict__ A,
                                          const float* __restrict__ B, int M, int outrow0,
                                          int by, int bx) {
    __shared__ alignas(16) float As[2][128][ALD];
    __shared__ alignas(16) float Bs[2][16][BLD];
    int t = threadIdx.x;
    int wid = t >> 5;
    int wr = wid >> 2;
    int wc = wid & 3;
    int brow0 = by * 128;
    int bcol0 = bx * 128;

    wmma::fragment<wmma::accumulator, 16, 16, 8, float> c[4][2];
#pragma unroll
    for (int i = 0; i < 4; i++)
#pragma unroll
        for (int j = 0; j < 2; j++) wmma::fill_fragment(c[i][j], 0.0f);

    int af0 = t * 2, af1 = t * 2 + 1;
    int ar0 = af0 >> 2, ac0 = (af0 & 3) << 2;
    int ar1 = af1 >> 2, ac1 = (af1 & 3) << 2;
    int br0 = af0 >> 5, bc0 = (af0 & 31) << 2;
    int br1 = af1 >> 5, bc1 = (af1 & 31) << 2;

#define CVT4(v)                                  \
    do {                                         \
        (v).x = wmma::__float_to_tf32((v).x);    \
        (v).y = wmma::__float_to_tf32((v).y);    \
        (v).z = wmma::__float_to_tf32((v).z);    \
        (v).w = wmma::__float_to_tf32((v).w);    \
    } while (0)

    {
        float4 z = make_float4(0.f, 0.f, 0.f, 0.f);
        float4 a0v = (brow0 + ar0 < M) ? *(const float4*)(A + (brow0 + ar0) * 256 + ac0) : z;
        float4 a1v = (brow0 + ar1 < M) ? *(const float4*)(A + (brow0 + ar1) * 256 + ac1) : z;
        float4 b0v = *(const float4*)(B + br0 * 256 + bcol0 + bc0);
        float4 b1v = *(const float4*)(B + br1 * 256 + bcol0 + bc1);
        CVT4(a0v); CVT4(a1v); CVT4(b0v); CVT4(b1v);
        *(float4*)&As[0][ar0][ac0] = a0v;
        *(float4*)&As[0][ar1][ac1] = a1v;
        *(float4*)&Bs[0][br0][bc0] = b0v;
        *(float4*)&Bs[0][br1][bc1] = b1v;
    }
    __syncthreads();
    int cur = 0;
    for (int k0 = 16; k0 <= 256; k0 += 16) {
        float4 a0v, a1v, b0v, b1v;
        if (k0 < 256) {
            float4 z = make_float4(0.f, 0.f, 0.f, 0.f);
            a0v = (brow0 + ar0 < M) ? *(const float4*)(A + (brow0 + ar0) * 256 + k0 + ac0) : z;
            a1v = (brow0 + ar1 < M) ? *(const float4*)(A + (brow0 + ar1) * 256 + k0 + ac1) : z;
            b0v = *(const float4*)(B + (k0 + br0) * 256 + bcol0 + bc0);
            b1v = *(const float4*)(B + (k0 + br1) * 256 + bcol0 + bc1);
        }
#pragma unroll
        for (int kk = 0; kk < 16; kk += 8) {
            wmma::fragment<wmma::matrix_a, 16, 16, 8, wmma::precision::tf32, wmma::row_major> a[4];
            wmma::fragment<wmma::matrix_b, 16, 16, 8, wmma::precision::tf32, wmma::row_major> b[2];
#pragma unroll
            for (int i = 0; i < 4; i++)
                wmma::load_matrix_sync(a[i], &As[cur][wr * 64 + i * 16][kk], ALD);
#pragma unroll
            for (int j = 0; j < 2; j++)
                wmma::load_matrix_sync(b[j], &Bs[cur][kk][wc * 32 + j * 16], BLD);
#pragma unroll
            for (int i = 0; i < 4; i++)
#pragma unroll
                for (int j = 0; j < 2; j++) wmma::mma_sync(c[i][j], a[i], b[j], c[i][j]);
        }
        if (k0 < 256) {
            int nxt = cur ^ 1;
            CVT4(a0v); CVT4(a1v); CVT4(b0v); CVT4(b1v);
            *(float4*)&As[nxt][ar0][ac0] = a0v;
            *(float4*)&As[nxt][ar1][ac1] = a1v;
            *(float4*)&Bs[nxt][br0][bc0] = b0v;
            *(float4*)&Bs[nxt][br1][bc1] = b1v;
            __syncthreads();
            cur = nxt;
        }
    }
#pragma unroll
    for (int i = 0; i < 4; i++)
#pragma unroll
        for (int j = 0; j < 2; j++)
            wmma::store_matrix_sync(
                g_tmp + (long)(outrow0 + brow0 + wr * 64 + i * 16) * 256 + bcol0 + wc * 32 +
                    j * 16,
                c[i][j], 256, wmma::mem_row_major);
#undef CVT4
}

__global__ void __launch_bounds__(256, 2)
k_gemm(const float* __restrict__ Aext, int awhich, const float* __restrict__ B, int M) {
    const float* A = (awhich < 0) ? Aext : BUF(awhich);
    gemm_body(A, B, M, 0, blockIdx.y, blockIdx.x);
}
__global__ void __launch_bounds__(256, 2)
k_gemm2(const float* __restrict__ x_ab, const float* __restrict__ W_ab,
        const float* __restrict__ x_ag, const float* __restrict__ W_ag) {
    if (blockIdx.z == 0) gemm_body(x_ab, W_ab, NAB, 0, blockIdx.y, blockIdx.x);
    else gemm_body(x_ag, W_ag, NAG, NAB, blockIdx.y, blockIdx.x);
}

// ---------------- merged GCN pull: 2 warps per dst (feature halves) ----------------
__global__ void k_gcn_pull2(const float* __restrict__ b_ab, const float* __restrict__ b_ag) {
    int w2 = (blockIdx.x * blockDim.x + threadIdx.x) >> 5;
    int lane = threadIdx.x & 31;
    int w = w2 >> 1;
    int half = w2 & 1;
    if (w >= NTOT) return;
    int fo = lane + half * 32;  // float4 index within row
    int g, local, tmprow;
    const float* b;
    if (w < NAB) { g = 0; local = w; tmprow = 0; b = b_ab; }
    else { g = 1; local = w - NAB; tmprow = NAB; b = b_ag; }
    int rb = g * NTOT;
    int r0 = g_rowg[rb + local], r1 = g_rowg[rb + local + 1];
    float dd = g_deg[w];
    float4 a0 = *((const float4*)(g_tmp + (long)(tmprow + local) * FDIM) + fo);
    float sc = dd * dd;
    a0.x *= sc; a0.y *= sc; a0.z *= sc; a0.w *= sc;
    int degbase = (g == 0) ? 0 : NAB;
    for (int j = r0; j < r1; j++) {
        int s = g_srt[j];
        float nm = g_deg[degbase + s] * dd;
        float4 v0 = *((const float4*)(g_tmp + (long)(tmprow + s) * FDIM) + fo);
        a0.x += v0.x * nm; a0.y += v0.y * nm; a0.z += v0.z * nm; a0.w += v0.w * nm;
    }
    float4 b0 = *((const float4*)b + fo);
    a0.x += b0.x; a0.y += b0.y; a0.z += b0.z; a0.w += b0.w;
    *((float4*)(g_h + (long)w * FDIM) + fo) = a0;
}

// ---------------- BN ----------------
__global__ void k_zero_stats() {
    g_csum[blockIdx.x][threadIdx.x] = 0.f;
    g_csq[blockIdx.x][threadIdx.x] = 0.f;
}
__global__ void k_colstats2() {
    int grp = blockIdx.x >> 8;
    int blk = blockIdx.x & 255;
    const float* x = grp ? (g_h + NAB * FDIM) : g_h;
    int nrows = grp ? NAG : NAB;
    int col = threadIdx.x;
    float s = 0.f, q = 0.f;
    for (int r = blk; r < nrows; r += 256) {
        float v = x[r * FDIM + col];
        s += v;
        q += v * v;
    }
    atomicAdd(&g_csum[grp][col], s);
    atomicAdd(&g_csq[grp][col], q);
}
__global__ void k_bn_relu2(const float* __restrict__ g_ab, const float* __restrict__ be_ab,
                           const float* __restrict__ g_ag, const float* __restrict__ be_ag) {
    int idx = blockIdx.x * blockDim.x + threadIdx.x;
    if (idx >= NTOT * 64) return;
    int row = idx >> 6;
    int slot = (row < NAB) ? 0 : 1;
    float n = (float)(slot ? NAG : NAB);
    const float* g = slot ? g_ag : g_ab;
    const float* be = slot ? be_ag : be_ab;
    int f = (idx & 63) << 2;
    float4 v = *((float4*)g_h + idx);
    float* pv = &v.x;
#pragma unroll
    for (int j = 0; j < 4; j++) {
        float mu = g_csum[slot][f + j] / n;
        float var = g_csq[slot][f + j] / n - mu * mu;
        float o = (pv[j] - mu) * rsqrtf(var + EPSV) * g[f + j] + be[f + j];
        pv[j] = o > 0.f ? o : 0.f;
    }
    *((float4*)g_h + idx) = v;
}
__global__ void k_colstats4() {
    int grp = blockIdx.x >> 8;
    int blk = blockIdx.x & 255;
    const float* x;
    int nrows;
    switch (grp) {
        case 0: x = g_xb; nrows = NAB; break;
        case 1: x = g_xb + NAB * FDIM; nrows = NAG; break;
        case 2: x = g_h; nrows = NAB; break;
        default: x = g_h + NAB * FDIM; nrows = NAG; break;
    }
    int col = threadIdx.x;
    float s = 0.f, q = 0.f;
    for (int r = blk; r < nrows; r += 256) {
        float v = x[r * FDIM + col];
        s += v;
        q += v * v;
    }
    atomicAdd(&g_csum[grp][col], s);
    atomicAdd(&g_csq[grp][col], q);
}

// ---------------- GAT ----------------
__global__ void k_dots(const float* __restrict__ a_s, const float* __restrict__ a_d) {
    int w = (blockIdx.x * blockDim.x + threadIdx.x) >> 5;
    int lane = threadIdx.x & 31;
    if (w >= NTOT) return;
    const float4* hp = (const float4*)(g_tmp + (long)w * FDIM);
    const float4* ap = (const float4*)a_s;
    const float4* dp = (const float4*)a_d;
    float s = 0.f, d = 0.f;
#pragma unroll
    for (int c = 0; c < 2; c++) {
        float4 hv = hp[lane + c * 32];
        float4 av = ap[lane + c * 32];
        float4 dv = dp[lane + c * 32];
        s += hv.x * av.x + hv.y * av.y + hv.z * av.z + hv.w * av.w;
        d += hv.x * dv.x + hv.y * dv.y + hv.z * dv.z + hv.w * dv.w;
    }
#pragma unroll
    for (int o = 16; o; o >>= 1) {
        s += __shfl_xor_sync(0xFFFFFFFFu, s, o);
        d += __shfl_xor_sync(0xFFFFFFFFu, d, o);
    }
    if (lane == 0) {
        g_es[w] = s;
        g_ed[w] = d;
    }
}
// 2 warps per dst (feature halves); logit softmax recomputed identically per warp
__global__ void k_gat_pull(int accwhich, const float* __restrict__ b, int dorelu) {
    int w2 = (blockIdx.x * blockDim.x + threadIdx.x) >> 5;
    int lane = threadIdx.x & 31;
    int w = w2 >> 1;
    int half = w2 & 1;
    if (w >= NTOT) return;
    int fo = lane + half * 32;
    int rb = 2 * NTOT;
    int r0 = g_rowg[rb + w], r1 = g_rowg[rb + w + 1];
    float edd = g_ed[w];
    float eself = lrelu(g_es[w] + edd);
    float m = eself;
    for (int j = r0 + lane; j < r1; j += 32) {
        m = fmaxf(m, lrelu(g_es[g_srt[j]] + edd));
    }
#pragma unroll
    for (int o = 16; o; o >>= 1) m = fmaxf(m, __shfl_xor_sync(0xFFFFFFFFu, m, o));
    float exs = __expf(eself - m);
    float ssum = exs;
    float4 a0 = *((const float4*)(g_tmp + (long)w * FDIM) + fo);
    a0.x *= exs; a0.y *= exs; a0.z *= exs; a0.w *= exs;
    for (int j = r0; j < r1; j++) {
        int s = g_srt[j];
        float ex = __expf(lrelu(g_es[s] + edd) - m);
        ssum += ex;
        float4 v0 = *((const float4*)(g_tmp + (long)s * FDIM) + fo);
        a0.x += v0.x * ex; a0.y += v0.y * ex; a0.z += v0.z * ex; a0.w += v0.w * ex;
    }
    float inv = 1.0f / ssum;
    float4 b0 = *((const float4*)b + fo);
    a0.x = a0.x * inv + b0.x; a0.y = a0.y * inv + b0.y;
    a0.z = a0.z * inv + b0.z; a0.w = a0.w * inv + b0.w;
    if (dorelu) {
        a0.x = fmaxf(a0.x, 0.f); a0.y = fmaxf(a0.y, 0.f);
        a0.z = fmaxf(a0.z, 0.f); a0.w = fmaxf(a0.w, 0.f);
    }
    *((float4*)(BUF(accwhich) + (long)w * FDIM) + fo) = a0;
}

// ---------------- final heads (grid = NTOT) ----------------
__global__ void k_head2(const float* __restrict__ g2, const float* __restrict__ be2,
                        const float* __restrict__ W_fc, const float* __restrict__ b_fc,
                        const float* __restrict__ ag_g2, const float* __restrict__ ag_be2,
                        const float* __restrict__ W_agfc, const float* __restrict__ b_agfc,
                        float* __restrict__ out) {
    __shared__ float red[8];
    int row = blockIdx.x;
    int t = threadIdx.x;
    int lane = t & 31, wid = t >> 5;
    const float *xpart, *hpart, *g, *be, *W, *b;
    int slot_x, slot_h, lrow;
    if (row < NAB) {
        lrow = row;
        xpart = g_xb; hpart = g_h;
        slot_x = 0; slot_h = 2;
        g = g2; be = be2; W = W_fc; b = b_fc;
    } else {
        lrow = row - NAB;
        xpart = g_xb + NAB * FDIM; hpart = g_h + NAB * FDIM;
        slot_x = 1; slot_h = 3;
        g = ag_g2; be = ag_be2; W = W_agfc; b = b_agfc;
    }
    float n = (float)NAB;  // NAB == NAG
    float mu1 = g_csum[slot_x][t] / n;
    float var1 = g_csq[slot_x][t] / n - mu1 * mu1;
    float v1 = (xpart[lrow * FDIM + t] - mu1) * rsqrtf(var1 + EPSV) * g[t] + be[t];
    v1 = v1 > 0.f ? v1 : 0.f;
    float mu2 = g_csum[slot_h][t] / n;
    float var2 = g_csq[slot_h][t] / n - mu2 * mu2;
    float v2 = (hpart[lrow * FDIM + t] - mu2) * rsqrtf(var2 + EPSV) * g[FDIM + t] + be[FDIM + t];
    v2 = v2 > 0.f ? v2 : 0.f;
    float p = v1 * W[t] + v2 * W[FDIM + t];
#pragma unroll
    for (int o = 16; o; o >>= 1) p += __shfl_xor_sync(0xFFFFFFFFu, p, o);
    if (lane == 0) red[wid] = p;
    __syncthreads();
    if (t == 0) {
        float acc = red[0];
#pragma unroll
        for (int i = 1; i < 8; i++) acc += red[i];
        out[row] = acc + b[0];
    }
}

// ---------------- host orchestration (launches ONLY) ----------------
static void run_gat(int inwhich, const float* W, const float* a_s, const float* a_d,
                    const float* b, int accwhich, int dorelu) {
    dim3 gg(2, (NTOT + 127) / 128);
    k_gemm<<<gg, 256>>>(nullptr, inwhich, W, NTOT);
    k_dots<<<(NTOT + 7) / 8, 256>>>(a_s, a_d);
    k_gat_pull<<<(2 * NTOT + 7) / 8, 256>>>(accwhich, b, dorelu);
}

extern "C" void kernel_launch(void* const* d_in, const int* in_sizes, int n_in, void* d_out,
                              int out_size) {
    const float* x_ab = (const float*)d_in[0];
    const float* x_ag = (const float*)d_in[1];
    const float* W_gcn = (const float*)d_in[2];
    const float* b_gcn = (const float*)d_in[3];
    const float* g1 = (const float*)d_in[4];
    const float* be1 = (const float*)d_in[5];
    const float* W_aggcn = (const float*)d_in[6];
    const float* b_aggcn = (const float*)d_in[7];
    const float* ag_g1 = (const float*)d_in[8];
    const float* ag_be1 = (const float*)d_in[9];
    const float* W_gat = (const float*)d_in[10];
    const float* a_src = (const float*)d_in[11];
    const float* a_dst = (const float*)d_in[12];
    const float* b_gat = (const float*)d_in[13];
    const float* W_gat2 = (const float*)d_in[14];
    const float* a_src2 = (const float*)d_in[15];
    const float* a_dst2 = (const float*)d_in[16];
    const float* b_gat2 = (const float*)d_in[17];
    const float* ag_g2 = (const float*)d_in[18];
    const float* ag_be2 = (const float*)d_in[19];
    const float* W_agfc = (const float*)d_in[20];
    const float* b_agfc = (const float*)d_in[21];
    const float* g2 = (const float*)d_in[22];
    const float* be2 = (const float*)d_in[23];
    const float* W_fc = (const float*)d_in[24];
    const float* b_fc = (const float*)d_in[25];
    const int* e_ab = (const int*)d_in[26];
    const int* e_ag = (const int*)d_in[27];
    const int* e_d = (const int*)d_in[28];
    float* out = (float*)d_out;

    // batched CSR build (all 3 graphs, global prefix; scan1 also zeroes BN stats)
    k_zero_csr<<<(CSRN + 255) / 256, 256>>>();
    k_hist_all<<<(ETOT + 255) / 256, 256>>>(e_ab + EAB, e_ag + EAG, e_d + ED);
    k_scan1<<<SCAN_BLOCKS, 1024>>>();
    k_scan2<<<1, 128>>>();
    k_scan3<<<SCAN_BLOCKS, 1024>>>();
    k_fill_all<<<(ETOT + 255) / 256, 256>>>(e_ab, e_ag, e_d);

    // both GCNs fused
    {
        dim3 gg(2, (NAB + 127) / 128, 2);
        k_gemm2<<<gg, 256>>>(x_ab, W_gcn, x_ag, W_aggcn);
        k_gcn_pull2<<<(2 * NTOT + 7) / 8, 256>>>(b_gcn, b_aggcn);
        k_colstats2<<<512, 256>>>();
        k_bn_relu2<<<(NTOT * 64 + 255) / 256, 256>>>(g1, be1, ag_g1, ag_be1);
    }

    // GAT layer 1: g_h(0) -> g_xa(1), relu
    run_gat(0, W_gat, a_src, a_dst, b_gat, 1, 1);
    // GAT layer 2: g_xa(1) -> g_xb(2), no relu
    run_gat(1, W_gat2, a_src2, a_dst2, b_gat2, 2, 0);

    // head stats + heads
    k_zero_stats<<<4, 256>>>();
    k_colstats4<<<1024, 256>>>();
    k_head2<<<NTOT, 256>>>(g2, be2, W_fc, b_fc, ag_g2, ag_be2, W_agfc, b_agfc, out);
}

// round 16
// speedup vs baseline: 1.0698x; 1.0585x over previous
#include <cuda_runtime.h>
#include <mma.h>
using namespace nvcuda;

#define NAB 20000
#define NAG 20000
#define NTOT 40000
#define FDIM 256
#define EAB 320000
#define EAG 320000
#define ED 640000
#define ETOT (EAB + EAG + ED)
#define EPSV 1e-5f
#define MPAD 40192
#define CSRN (3 * NTOT)
#define SCAN_BLOCKS ((CSRN + 1023) / 1024)
#define ALD 20
#define BLD 132

// ---------------- scratch (device globals; no allocs) ----------------
__device__ float g_h[NTOT * FDIM];    // 0
__device__ float g_xa[NTOT * FDIM];   // 1
__device__ float g_xb[NTOT * FDIM];   // 2
__device__ float g_tmp[MPAD * FDIM];  // 3
__device__ float g_deg[NTOT];
__device__ float g_es[NTOT];
__device__ float g_ed[NTOT];
__device__ float g_csum[4][FDIM];
__device__ float g_csq[4][FDIM];
__device__ int g_cnt[CSRN];
__device__ int g_rowg[CSRN + 1];
__device__ int g_bsum[SCAN_BLOCKS];
__device__ int g_srt[ETOT];

__device__ __forceinline__ float* BUF(int which) {
    switch (which) {
        case 0: return g_h;
        case 1: return g_xa;
        case 2: return g_xb;
        default: return g_tmp;
    }
}

__device__ __forceinline__ float lrelu(float x) { return x > 0.f ? x : 0.2f * x; }

// ---------------- batched CSR build ----------------
__global__ void k_zero_csr() {
    int i = blockIdx.x * blockDim.x + threadIdx.x;
    if (i < CSRN) g_cnt[i] = 0;
}
__global__ void k_hist_all(const int* __restrict__ dab, const int* __restrict__ dag,
                           const int* __restrict__ dd) {
    int e = blockIdx.x * blockDim.x + threadIdx.x;
    if (e < EAB) atomicAdd(&g_cnt[0 * NTOT + dab[e]], 1);
    else if (e < EAB + EAG) atomicAdd(&g_cnt[1 * NTOT + dag[e - EAB]], 1);
    else if (e < ETOT) atomicAdd(&g_cnt[2 * NTOT + dd[e - EAB - EAG]], 1);
}
__global__ void k_scan1() {
    __shared__ int wsum[32];
    int gi = blockIdx.x * 1024 + threadIdx.x;
    int v = (gi < CSRN) ? g_cnt[gi] : 0;
    if (gi < NAB) g_deg[gi] = rsqrtf((float)(v + 1));
    else if (gi >= NTOT && gi < NTOT + NAG) g_deg[NAB + gi - NTOT] = rsqrtf((float)(v + 1));
    if (gi < 4 * FDIM) {  // fused zero of BN stat slots 0-3
        ((float*)g_csum)[gi] = 0.f;
        ((float*)g_csq)[gi] = 0.f;
    }
    int lane = threadIdx.x & 31, wid = threadIdx.x >> 5;
    int inc = v;
#pragma unroll
    for (int o = 1; o < 32; o <<= 1) {
        int u = __shfl_up_sync(0xFFFFFFFFu, inc, o);
        if (lane >= o) inc += u;
    }
    if (lane == 31) wsum[wid] = inc;
    __syncthreads();
    if (wid == 0) {
        int w = wsum[lane];
#pragma unroll
        for (int o = 1; o < 32; o <<= 1) {
            int u = __shfl_up_sync(0xFFFFFFFFu, w, o);
            if (lane >= o) w += u;
        }
        wsum[lane] = w;
    }
    __syncthreads();
    int ex = inc - v + (wid ? wsum[wid - 1] : 0);
    if (gi < CSRN) g_rowg[gi] = ex;
    if (threadIdx.x == 1023) g_bsum[blockIdx.x] = ex + v;
}
__global__ void k_scan2() {
    __shared__ int ws[4];
    int t = threadIdx.x;
    int lane = t & 31, wid = t >> 5;
    int v = (t < SCAN_BLOCKS) ? g_bsum[t] : 0;
    int inc = v;
#pragma unroll
    for (int o = 1; o < 32; o <<= 1) {
        int u = __shfl_up_sync(0xFFFFFFFFu, inc, o);
        if (lane >= o) inc += u;
    }
    if (lane == 31) ws[wid] = inc;
    __syncthreads();
    int add = 0;
    for (int i = 0; i < wid; i++) add += ws[i];
    if (t < SCAN_BLOCKS) g_bsum[t] = inc - v + add;
}
__global__ void k_scan3() {
    int gi = blockIdx.x * 1024 + threadIdx.x;
    if (gi < CSRN) {
        int r = g_rowg[gi] + g_bsum[blockIdx.x];
        g_rowg[gi] = r;
        g_cnt[gi] = r;
    }
    if (gi == 0) g_rowg[CSRN] = ETOT;
}
__global__ void k_fill_all(const int* __restrict__ eab, const int* __restrict__ eag,
                           const int* __restrict__ ed) {
    int e = blockIdx.x * blockDim.x + threadIdx.x;
    int g, le;
    const int* src;
    const int* dst;
    if (e < EAB) { g = 0; le = e; src = eab; dst = eab + EAB; }
    else if (e < EAB + EAG) { g = 1; le = e - EAB; src = eag; dst = eag + EAG; }
    else if (e < ETOT) { g = 2; le = e - EAB - EAG; src = ed; dst = ed + ED; }
    else return;
    int d = dst[le];
    int pos = atomicAdd(&g_cnt[g * NTOT + d], 1);
    g_srt[pos] = src[le];
}

// ---------------- TF32 wmma GEMM core ----------------
__device__ __forceinline__ void gemm_body(const float* __restrict__ A,
                                          const float* __restrict__ B, int M, int outrow0,
                                          int by, int bx) {
    __shared__ alignas(16) float As[2][128][ALD];
    __shared__ alignas(16) float Bs[2][16][BLD];
    int t = threadIdx.x;
    int wid = t >> 5;
    int wr = wid >> 2;
    int wc = wid & 3;
    int brow0 = by * 128;
    int bcol0 = bx * 128;

    wmma::fragment<wmma::accumulator, 16, 16, 8, float> c[4][2];
#pragma unroll
    for (int i = 0; i < 4; i++)
#pragma unroll
        for (int j = 0; j < 2; j++) wmma::fill_fragment(c[i][j], 0.0f);

    int af0 = t * 2, af1 = t * 2 + 1;
    int ar0 = af0 >> 2, ac0 = (af0 & 3) << 2;
    int ar1 = af1 >> 2, ac1 = (af1 & 3) << 2;
    int br0 = af0 >> 5, bc0 = (af0 & 31) << 2;
    int br1 = af1 >> 5, bc1 = (af1 & 31) << 2;

#define CVT4(v)                                  \
    do {                                         \
        (v).x = wmma::__float_to_tf32((v).x);    \
        (v).y = wmma::__float_to_tf32((v).y);    \
        (v).z = wmma::__float_to_tf32((v).z);    \
        (v).w = wmma::__float_to_tf32((v).w);    \
    } while (0)

    {
        float4 z = make_float4(0.f, 0.f, 0.f, 0.f);
        float4 a0v = (brow0 + ar0 < M) ? *(const float4*)(A + (brow0 + ar0) * 256 + ac0) : z;
        float4 a1v = (brow0 + ar1 < M) ? *(const float4*)(A + (brow0 + ar1) * 256 + ac1) : z;
        float4 b0v = *(const float4*)(B + br0 * 256 + bcol0 + bc0);
        float4 b1v = *(const float4*)(B + br1 * 256 + bcol0 + bc1);
        CVT4(a0v); CVT4(a1v); CVT4(b0v); CVT4(b1v);
        *(float4*)&As[0][ar0][ac0] = a0v;
        *(float4*)&As[0][ar1][ac1] = a1v;
        *(float4*)&Bs[0][br0][bc0] = b0v;
        *(float4*)&Bs[0][br1][bc1] = b1v;
    }
    __syncthreads();
    int cur = 0;
    for (int k0 = 16; k0 <= 256; k0 += 16) {
        float4 a0v, a1v, b0v, b1v;
        if (k0 < 256) {
            float4 z = make_float4(0.f, 0.f, 0.f, 0.f);
            a0v = (brow0 + ar0 < M) ? *(const float4*)(A + (brow0 + ar0) * 256 + k0 + ac0) : z;
            a1v = (brow0 + ar1 < M) ? *(const float4*)(A + (brow0 + ar1) * 256 + k0 + ac1) : z;
            b0v = *(const float4*)(B + (k0 + br0) * 256 + bcol0 + bc0);
            b1v = *(const float4*)(B + (k0 + br1) * 256 + bcol0 + bc1);
        }
#pragma unroll
        for (int kk = 0; kk < 16; kk += 8) {
            wmma::fragment<wmma::matrix_a, 16, 16, 8, wmma::precision::tf32, wmma::row_major> a[4];
            wmma::fragment<wmma::matrix_b, 16, 16, 8, wmma::precision::tf32, wmma::row_major> b[2];
#pragma unroll
            for (int i = 0; i < 4; i++)
                wmma::load_matrix_sync(a[i], &As[cur][wr * 64 + i * 16][kk], ALD);
#pragma unroll
            for (int j = 0; j < 2; j++)
                wmma::load_matrix_sync(b[j], &Bs[cur][kk][wc * 32 + j * 16], BLD);
#pragma unroll
            for (int i = 0; i < 4; i++)
#pragma unroll
                for (int j = 0; j < 2; j++) wmma::mma_sync(c[i][j], a[i], b[j], c[i][j]);
        }
        if (k0 < 256) {
            int nxt = cur ^ 1;
            CVT4(a0v); CVT4(a1v); CVT4(b0v); CVT4(b1v);
            *(float4*)&As[nxt][ar0][ac0] = a0v;
            *(float4*)&As[nxt][ar1][ac1] = a1v;
            *(float4*)&Bs[nxt][br0][bc0] = b0v;
            *(float4*)&Bs[nxt][br1][bc1] = b1v;
            __syncthreads();
            cur = nxt;
        }
    }
#pragma unroll
    for (int i = 0; i < 4; i++)
#pragma unroll
        for (int j = 0; j < 2; j++)
            wmma::store_matrix_sync(
                g_tmp + (long)(outrow0 + brow0 + wr * 64 + i * 16) * 256 + bcol0 + wc * 32 +
                    j * 16,
                c[i][j], 256, wmma::mem_row_major);
#undef CVT4
}

__global__ void __launch_bounds__(256, 2)
k_gemm(const float* __restrict__ Aext, int awhich, const float* __restrict__ B, int M) {
    const float* A = (awhich < 0) ? Aext : BUF(awhich);
    gemm_body(A, B, M, 0, blockIdx.y, blockIdx.x);
}
__global__ void __launch_bounds__(256, 2)
k_gemm2(const float* __restrict__ x_ab, const float* __restrict__ W_ab,
        const float* __restrict__ x_ag, const float* __restrict__ W_ag) {
    if (blockIdx.z == 0) gemm_body(x_ab, W_ab, NAB, 0, blockIdx.y, blockIdx.x);
    else gemm_body(x_ag, W_ag, NAG, NAB, blockIdx.y, blockIdx.x);
}

// ---------------- merged GCN pull: warp per dst (R12 form) ----------------
__global__ void k_gcn_pull2(const float* __restrict__ b_ab, const float* __restrict__ b_ag) {
    int w = (blockIdx.x * blockDim.x + threadIdx.x) >> 5;
    int lane = threadIdx.x & 31;
    if (w >= NTOT) return;
    int g, local, tmprow;
    const float* b;
    if (w < NAB) { g = 0; local = w; tmprow = 0; b = b_ab; }
    else { g = 1; local = w - NAB; tmprow = NAB; b = b_ag; }
    int rb = g * NTOT;
    int r0 = g_rowg[rb + local], r1 = g_rowg[rb + local + 1];
    float dd = g_deg[w];
    const float4* hp = (const float4*)(g_tmp + (long)(tmprow + local) * FDIM);
    float4 a0 = hp[lane];
    float4 a1 = hp[lane + 32];
    float sc = dd * dd;
    a0.x *= sc; a0.y *= sc; a0.z *= sc; a0.w *= sc;
    a1.x *= sc; a1.y *= sc; a1.z *= sc; a1.w *= sc;
    int degbase = (g == 0) ? 0 : NAB;
    for (int j = r0; j < r1; j++) {
        int s = g_srt[j];
        float nm = g_deg[degbase + s] * dd;
        const float4* sp = (const float4*)(g_tmp + (long)(tmprow + s) * FDIM);
        float4 v0 = sp[lane];
        float4 v1 = sp[lane + 32];
        a0.x += v0.x * nm; a0.y += v0.y * nm; a0.z += v0.z * nm; a0.w += v0.w * nm;
        a1.x += v1.x * nm; a1.y += v1.y * nm; a1.z += v1.z * nm; a1.w += v1.w * nm;
    }
    float4 b0 = *((const float4*)b + lane);
    float4 b1 = *((const float4*)b + lane + 32);
    a0.x += b0.x; a0.y += b0.y; a0.z += b0.z; a0.w += b0.w;
    a1.x += b1.x; a1.y += b1.y; a1.z += b1.z; a1.w += b1.w;
    float4* op = (float4*)(g_h + (long)w * FDIM);
    op[lane] = a0;
    op[lane + 32] = a1;
}

// ---------------- BN ----------------
__global__ void k_zero_stats() {  // gridDim slots starting at 0
    g_csum[blockIdx.x][threadIdx.x] = 0.f;
    g_csq[blockIdx.x][threadIdx.x] = 0.f;
}
__global__ void k_colstats2() {
    int grp = blockIdx.x >> 8;
    int blk = blockIdx.x & 255;
    const float* x = grp ? (g_h + NAB * FDIM) : g_h;
    int nrows = grp ? NAG : NAB;
    int col = threadIdx.x;
    float s = 0.f, q = 0.f;
    for (int r = blk; r < nrows; r += 256) {
        float v = x[r * FDIM + col];
        s += v;
        q += v * v;
    }
    atomicAdd(&g_csum[grp][col], s);
    atomicAdd(&g_csq[grp][col], q);
}
__global__ void k_bn_relu2(const float* __restrict__ g_ab, const float* __restrict__ be_ab,
                           const float* __restrict__ g_ag, const float* __restrict__ be_ag) {
    int idx = blockIdx.x * blockDim.x + threadIdx.x;
    if (idx >= NTOT * 64) return;
    int row = idx >> 6;
    int slot = (row < NAB) ? 0 : 1;
    float n = (float)(slot ? NAG : NAB);
    const float* g = slot ? g_ag : g_ab;
    const float* be = slot ? be_ag : be_ab;
    int f = (idx & 63) << 2;
    float4 v = *((float4*)g_h + idx);
    float* pv = &v.x;
#pragma unroll
    for (int j = 0; j < 4; j++) {
        float mu = g_csum[slot][f + j] / n;
        float var = g_csq[slot][f + j] / n - mu * mu;
        float o = (pv[j] - mu) * rsqrtf(var + EPSV) * g[f + j] + be[f + j];
        pv[j] = o > 0.f ? o : 0.f;
    }
    *((float4*)g_h + idx) = v;
}
// head stats for g_h halves -> slots 2,3 ; also zeroes slots 0,1 first blocks
__global__ void k_colstats_h() {
    int grp = blockIdx.x >> 8;  // 0,1 -> slots 2,3
    int blk = blockIdx.x & 255;
    if (blockIdx.x < 2 && threadIdx.x < 256) {  // zero slots 0,1 (one block each)
        // blocks 0 and 1 additionally zero slot (blockIdx.x)
        g_csum[blockIdx.x][threadIdx.x] = 0.f;
        g_csq[blockIdx.x][threadIdx.x] = 0.f;
    }
    const float* x = grp ? (g_h + NAB * FDIM) : g_h;
    int nrows = grp ? NAG : NAB;
    int slot = 2 + grp;
    int col = threadIdx.x;
    float s = 0.f, q = 0.f;
    for (int r = blk; r < nrows; r += 256) {
        float v = x[r * FDIM + col];
        s += v;
        q += v * v;
    }
    atomicAdd(&g_csum[slot][col], s);
    atomicAdd(&g_csq[slot][col], q);
}
// head stats for g_xb halves -> slots 0,1
__global__ void k_colstats_x() {
    int grp = blockIdx.x >> 8;
    int blk = blockIdx.x & 255;
    const float* x = grp ? (g_xb + NAB * FDIM) : g_xb;
    int nrows = grp ? NAG : NAB;
    int col = threadIdx.x;
    float s = 0.f, q = 0.f;
    for (int r = blk; r < nrows; r += 256) {
        float v = x[r * FDIM + col];
        s += v;
        q += v * v;
    }
    atomicAdd(&g_csum[grp][col], s);
    atomicAdd(&g_csq[grp][col], q);
}

// ---------------- GAT ----------------
__global__ void k_dots(const float* __restrict__ a_s, const float* __restrict__ a_d) {
    int w = (blockIdx.x * blockDim.x + threadIdx.x) >> 5;
    int lane = threadIdx.x & 31;
    if (w >= NTOT) return;
    const float4* hp = (const float4*)(g_tmp + (long)w * FDIM);
    const float4* ap = (const float4*)a_s;
    const float4* dp = (const float4*)a_d;
    float s = 0.f, d = 0.f;
#pragma unroll
    for (int c = 0; c < 2; c++) {
        float4 hv = hp[lane + c * 32];
        float4 av = ap[lane + c * 32];
        float4 dv = dp[lane + c * 32];
        s += hv.x * av.x + hv.y * av.y + hv.z * av.z + hv.w * av.w;
        d += hv.x * dv.x + hv.y * dv.y + hv.z * dv.z + hv.w * dv.w;
    }
#pragma unroll
    for (int o = 16; o; o >>= 1) {
        s += __shfl_xor_sync(0xFFFFFFFFu, s, o);
        d += __shfl_xor_sync(0xFFFFFFFFu, d, o);
    }
    if (lane == 0) {
        g_es[w] = s;
        g_ed[w] = d;
    }
}
// warp per dst (R12 form)
__global__ void k_gat_pull(int accwhich, const float* __restrict__ b, int dorelu) {
    int w = (blockIdx.x * blockDim.x + threadIdx.x) >> 5;
    int lane = threadIdx.x & 31;
    if (w >= NTOT) return;
    int rb = 2 * NTOT;
    int r0 = g_rowg[rb + w], r1 = g_rowg[rb + w + 1];
    float edd = g_ed[w];
    float eself = lrelu(g_es[w] + edd);
    float m = eself;
    for (int j = r0 + lane; j < r1; j += 32) {
        m = fmaxf(m, lrelu(g_es[g_srt[j]] + edd));
    }
#pragma unroll
    for (int o = 16; o; o >>= 1) m = fmaxf(m, __shfl_xor_sync(0xFFFFFFFFu, m, o));
    float exs = __expf(eself - m);
    float ssum = exs;
    const float4* hp = (const float4*)(g_tmp + (long)w * FDIM);
    float4 a0 = hp[lane];
    float4 a1 = hp[lane + 32];
    a0.x *= exs; a0.y *= exs; a0.z *= exs; a0.w *= exs;
    a1.x *= exs; a1.y *= exs; a1.z *= exs; a1.w *= exs;
    for (int j = r0; j < r1; j++) {
        int s = g_srt[j];
        float ex = __expf(lrelu(g_es[s] + edd) - m);
        ssum += ex;
        const float4* sp = (const float4*)(g_tmp + (long)s * FDIM);
        float4 v0 = sp[lane];
        float4 v1 = sp[lane + 32];
        a0.x += v0.x * ex; a0.y += v0.y * ex; a0.z += v0.z * ex; a0.w += v0.w * ex;
        a1.x += v1.x * ex; a1.y += v1.y * ex; a1.z += v1.z * ex; a1.w += v1.w * ex;
    }
    float inv = 1.0f / ssum;
    float4 b0 = *((const float4*)b + lane);
    float4 b1 = *((const float4*)b + lane + 32);
    a0.x = a0.x * inv + b0.x; a0.y = a0.y * inv + b0.y;
    a0.z = a0.z * inv + b0.z; a0.w = a0.w * inv + b0.w;
    a1.x = a1.x * inv + b1.x; a1.y = a1.y * inv + b1.y;
    a1.z = a1.z * inv + b1.z; a1.w = a1.w * inv + b1.w;
    if (dorelu) {
        a0.x = fmaxf(a0.x, 0.f); a0.y = fmaxf(a0.y, 0.f);
        a0.z = fmaxf(a0.z, 0.f); a0.w = fmaxf(a0.w, 0.f);
        a1.x = fmaxf(a1.x, 0.f); a1.y = fmaxf(a1.y, 0.f);
        a1.z = fmaxf(a1.z, 0.f); a1.w = fmaxf(a1.w, 0.f);
    }
    float4* op = (float4*)(BUF(accwhich) + (long)w * FDIM);
    op[lane] = a0;
    op[lane + 32] = a1;
}

// ---------------- final heads (grid = NTOT) ----------------
__global__ void k_head2(const float* __restrict__ g2, const float* __restrict__ be2,
                        const float* __restrict__ W_fc, const float* __restrict__ b_fc,
                        const float* __restrict__ ag_g2, const float* __restrict__ ag_be2,
                        const float* __restrict__ W_agfc, const float* __restrict__ b_agfc,
                        float* __restrict__ out) {
    __shared__ float red[8];
    int row = blockIdx.x;
    int t = threadIdx.x;
    int lane = t & 31, wid = t >> 5;
    const float *xpart, *hpart, *g, *be, *W, *b;
    int slot_x, slot_h, lrow;
    if (row < NAB) {
        lrow = row;
        xpart = g_xb; hpart = g_h;
        slot_x = 0; slot_h = 2;
        g = g2; be = be2; W = W_fc; b = b_fc;
    } else {
        lrow = row - NAB;
        xpart = g_xb + NAB * FDIM; hpart = g_h + NAB * FDIM;
        slot_x = 1; slot_h = 3;
        g = ag_g2; be = ag_be2; W = W_agfc; b = b_agfc;
    }
    float n = (float)NAB;  // NAB == NAG
    float mu1 = g_csum[slot_x][t] / n;
    float var1 = g_csq[slot_x][t] / n - mu1 * mu1;
    float v1 = (xpart[lrow * FDIM + t] - mu1) * rsqrtf(var1 + EPSV) * g[t] + be[t];
    v1 = v1 > 0.f ? v1 : 0.f;
    float mu2 = g_csum[slot_h][t] / n;
    float var2 = g_csq[slot_h][t] / n - mu2 * mu2;
    float v2 = (hpart[lrow * FDIM + t] - mu2) * rsqrtf(var2 + EPSV) * g[FDIM + t] + be[FDIM + t];
    v2 = v2 > 0.f ? v2 : 0.f;
    float p = v1 * W[t] + v2 * W[FDIM + t];
#pragma unroll
    for (int o = 16; o; o >>= 1) p += __shfl_xor_sync(0xFFFFFFFFu, p, o);
    if (lane == 0) red[wid] = p;
    __syncthreads();
    if (t == 0) {
        float acc = red[0];
#pragma unroll
        for (int i = 1; i < 8; i++) acc += red[i];
        out[row] = acc + b[0];
    }
}

// ---------------- host orchestration (launches + capture-legal fork/join) ----------------
extern "C" void kernel_launch(void* const* d_in, const int* in_sizes, int n_in, void* d_out,
                              int out_size) {
    const float* x_ab = (const float*)d_in[0];
    const float* x_ag = (const float*)d_in[1];
    const float* W_gcn = (const float*)d_in[2];
    const float* b_gcn = (const float*)d_in[3];
    const float* g1 = (const float*)d_in[4];
    const float* be1 = (const float*)d_in[5];
    const float* W_aggcn = (const float*)d_in[6];
    const float* b_aggcn = (const float*)d_in[7];
    const float* ag_g1 = (const float*)d_in[8];
    const float* ag_be1 = (const float*)d_in[9];
    const float* W_gat = (const float*)d_in[10];
    const float* a_src = (const float*)d_in[11];
    const float* a_dst = (const float*)d_in[12];
    const float* b_gat = (const float*)d_in[13];
    const float* W_gat2 = (const float*)d_in[14];
    const float* a_src2 = (const float*)d_in[15];
    const float* a_dst2 = (const float*)d_in[16];
    const float* b_gat2 = (const float*)d_in[17];
    const float* ag_g2 = (const float*)d_in[18];
    const float* ag_be2 = (const float*)d_in[19];
    const float* W_agfc = (const float*)d_in[20];
    const float* b_agfc = (const float*)d_in[21];
    const float* g2 = (const float*)d_in[22];
    const float* be2 = (const float*)d_in[23];
    const float* W_fc = (const float*)d_in[24];
    const float* b_fc = (const float*)d_in[25];
    const int* e_ab = (const int*)d_in[26];
    const int* e_ag = (const int*)d_in[27];
    const int* e_d = (const int*)d_in[28];
    float* out = (float*)d_out;

    cudaStream_t s2;
    cudaStreamCreateWithFlags(&s2, cudaStreamNonBlocking);
    cudaEvent_t evFork1, evJoin1, evFork2, evJoin2;
    cudaEventCreateWithFlags(&evFork1, cudaEventDisableTiming);
    cudaEventCreateWithFlags(&evJoin1, cudaEventDisableTiming);
    cudaEventCreateWithFlags(&evFork2, cudaEventDisableTiming);
    cudaEventCreateWithFlags(&evJoin2, cudaEventDisableTiming);

    // fork: CSR build on s2, GCN dual-GEMM on main (independent)
    cudaEventRecord(evFork1, 0);
    cudaStreamWaitEvent(s2, evFork1, 0);
    k_zero_csr<<<(CSRN + 255) / 256, 256, 0, s2>>>();
    k_hist_all<<<(ETOT + 255) / 256, 256, 0, s2>>>(e_ab + EAB, e_ag + EAG, e_d + ED);
    k_scan1<<<SCAN_BLOCKS, 1024, 0, s2>>>();
    k_scan2<<<1, 128, 0, s2>>>();
    k_scan3<<<SCAN_BLOCKS, 1024, 0, s2>>>();
    k_fill_all<<<(ETOT + 255) / 256, 256, 0, s2>>>(e_ab, e_ag, e_d);
    cudaEventRecord(evJoin1, s2);

    {
        dim3 gg(2, (NAB + 127) / 128, 2);
        k_gemm2<<<gg, 256>>>(x_ab, W_gcn, x_ag, W_aggcn);
    }
    cudaStreamWaitEvent(0, evJoin1, 0);  // join: pull needs CSR + GEMM

    k_gcn_pull2<<<(NTOT + 7) / 8, 256>>>(b_gcn, b_aggcn);
    k_colstats2<<<512, 256>>>();
    k_bn_relu2<<<(NTOT * 64 + 255) / 256, 256>>>(g1, be1, ag_g1, ag_be1);

    // fork: g_h head-stats (slots 2,3) + zero slots 0,1 on s2, under GAT phase
    cudaEventRecord(evFork2, 0);
    cudaStreamWaitEvent(s2, evFork2, 0);
    k_colstats_h<<<512, 256, 0, s2>>>();
    cudaEventRecord(evJoin2, s2);

    // GAT layer 1: g_h(0) -> g_xa(1), relu
    {
        dim3 gg(2, (NTOT + 127) / 128);
        k_gemm<<<gg, 256>>>(nullptr, 0, W_gat, NTOT);
        k_dots<<<(NTOT + 7) / 8, 256>>>(a_src, a_dst);
        k_gat_pull<<<(NTOT + 7) / 8, 256>>>(1, b_gat, 1);
    }
    // GAT layer 2: g_xa(1) -> g_xb(2), no relu
    {
        dim3 gg(2, (NTOT + 127) / 128);
        k_gemm<<<gg, 256>>>(nullptr, 1, W_gat2, NTOT);
        k_dots<<<(NTOT + 7) / 8, 256>>>(a_src2, a_dst2);
        k_gat_pull<<<(NTOT + 7) / 8, 256>>>(2, b_gat2, 0);
    }

    cudaStreamWaitEvent(0, evJoin2, 0);  // join: slots 0,1 zeroed; slots 2,3 ready
    k_colstats_x<<<512, 256>>>();
    k_head2<<<NTOT, 256>>>(g2, be2, W_fc, b_fc, ag_g2, ag_be2, W_agfc, b_agfc, out);

    cudaEventDestroy(evFork1);
    cudaEventDestroy(evJoin1);
    cudaEventDestroy(evFork2);
    cudaEventDestroy(evJoin2);
    cudaStreamDestroy(s2);
}